// round 14
// baseline (speedup 1.0000x reference)
#include <cuda_runtime.h>
#include <cuda_bf16.h>
#include <math.h>
#include <stdint.h>

// Problem constants
#define BSZ   8
#define TT    8
#define HW    1024
#define CK    256
#define CV    3
#define MEM   512
#define NPAIR 56
#define NQ    (NPAIR * HW)     // 57344 queries total
#define COEF_MEM 0.2f
// k and m_k are pre-scaled by sqrt(log2(e)) in prep, so accumulated logits
// are logit*log2(e); softmax uses ex2 directly with a constant shift.
#define SQRT_LOG2E 1.20112240878645f
#define SOFTMAX_SHIFT2 57.7078016355585f   // 40 * log2(e)

// Scratch (static device arrays; no allocs)
__device__ __nv_bfloat16 g_khi[(size_t)BSZ * TT * HW * CK];
__device__ __nv_bfloat16 g_klo[(size_t)BSZ * TT * HW * CK];
__device__ __nv_bfloat16 g_mkhi[(size_t)BSZ * TT * MEM * CK];
__device__ __nv_bfloat16 g_mklo[(size_t)BSZ * TT * MEM * CK];
// Partial softmax state: [split 0..2][query][4] = {s, a0, a1, a2}
__device__ float g_part[(size_t)3 * NQ * 4];

// ---------------------------------------------------------------------------
// Baseline-PTX helpers (sm_80+ portable)
// ---------------------------------------------------------------------------
__device__ __forceinline__ uint32_t smem_u32(const void* p) {
    uint32_t a;
    asm("{ .reg .u64 t; cvta.to.shared.u64 t, %1; cvt.u32.u64 %0, t; }"
        : "=r"(a) : "l"(p));
    return a;
}

__device__ __forceinline__ float ex2f(float x) {
    float r;
    asm("ex2.approx.f32 %0, %1;" : "=f"(r) : "f"(x));
    return r;
}

#define CP_ASYNC16(dst, src) \
    asm volatile("cp.async.cg.shared.global [%0], [%1], 16;" \
                 :: "r"(dst), "l"(src))
#define CP_ASYNC4(dst, src) \
    asm volatile("cp.async.ca.shared.global [%0], [%1], 4;" \
                 :: "r"(dst), "l"(src))
#define CP_COMMIT() asm volatile("cp.async.commit_group;" ::: "memory")
#define CP_WAIT1()  asm volatile("cp.async.wait_group 1;" ::: "memory")

#define LDSM_X4(r0, r1, r2, r3, addr) \
    asm volatile("ldmatrix.sync.aligned.m8n8.x4.shared.b16 {%0,%1,%2,%3}, [%4];" \
                 : "=r"(r0), "=r"(r1), "=r"(r2), "=r"(r3) : "r"(addr))

#define MMA_BF16(d, a, b) \
    asm volatile("mma.sync.aligned.m16n8k16.row.col.f32.bf16.bf16.f32 " \
                 "{%0,%1,%2,%3}, {%4,%5,%6,%7}, {%8,%9}, {%0,%1,%2,%3};" \
                 : "+f"((d)[0]), "+f"((d)[1]), "+f"((d)[2]), "+f"((d)[3]) \
                 : "r"((a)[0]), "r"((a)[1]), "r"((a)[2]), "r"((a)[3]), \
                   "r"((b)[0]), "r"((b)[1]))

// ---------------------------------------------------------------------------
// Prep kernel (single launch): fp32 -> bf16 hi/lo split for k and m_k,
// pre-scaled by sqrt(log2(e)) so logits land in the exp2 domain.
// ---------------------------------------------------------------------------
#define NK4  ((BSZ * TT * HW * CK) / 4)
#define NMK4 ((BSZ * TT * MEM * CK) / 4)

__global__ __launch_bounds__(256)
void prep_kernel(const float* __restrict__ k, const float* __restrict__ m_k)
{
    int i = blockIdx.x * blockDim.x + threadIdx.x;
    const float* src;
    __nv_bfloat162 *hp, *lp;
    int idx;
    if (i < NK4) {
        src = k; idx = i;
        hp = (__nv_bfloat162*)g_khi; lp = (__nv_bfloat162*)g_klo;
    } else if (i < NK4 + NMK4) {
        src = m_k; idx = i - NK4;
        hp = (__nv_bfloat162*)g_mkhi; lp = (__nv_bfloat162*)g_mklo;
    } else {
        return;
    }
    float4 x = ((const float4*)src)[idx];
    x.x *= SQRT_LOG2E; x.y *= SQRT_LOG2E; x.z *= SQRT_LOG2E; x.w *= SQRT_LOG2E;
    __nv_bfloat16 h0 = __float2bfloat16(x.x), h1 = __float2bfloat16(x.y);
    __nv_bfloat16 h2 = __float2bfloat16(x.z), h3 = __float2bfloat16(x.w);
    __nv_bfloat16 l0 = __float2bfloat16(x.x - __bfloat162float(h0));
    __nv_bfloat16 l1 = __float2bfloat16(x.y - __bfloat162float(h1));
    __nv_bfloat16 l2 = __float2bfloat16(x.z - __bfloat162float(h2));
    __nv_bfloat16 l3 = __float2bfloat16(x.w - __bfloat162float(h3));
    hp[2 * idx] = {h0, h1}; hp[2 * idx + 1] = {h2, h3};
    lp[2 * idx] = {l0, l1}; lp[2 * idx + 1] = {l2, l3};
}

// ---------------------------------------------------------------------------
// Fused kernel: per CTA, 128 queries x 512 keys (one split).
// Per 128-key chunk: logits via 3-term bf16-split mma.sync; the (additive,
// constant-shift, exp2-domain) softmax epilogue of chunk c is DISTRIBUTED
// across the 8 slices of chunk c+1 (acc double-buffer).
// 8 warps = 4m x 2n, warp tile 32 rows x 64 cols.
// K streamed in 32-ck slices, triple-buffered cp.async. Q resident in SMEM.
// V loaded via cp.async (4B), consumed one chunk later (latency hidden).
// ---------------------------------------------------------------------------
#define SM_QHI 0
#define SM_QLO 65536
#define SM_K   131072               // 3 bufs x 16384 (hi 8KB + lo 8KB)
#define SM_V   180224               // 2 bufs x 128 x float4 = 4096
#define SM_RED 184320               // 2KB: [128] float4 for final merge
#define FUSED_SMEM 186368

struct Ctx {
    uint32_t sb;
    const __nv_bfloat16 *khiP, *kloP;
    const float* vP;
    int tid, wm, wn, grp_d0, grp_dk, irow, tau;
    int lr, ljb;
    uint32_t ldrow;
    char* smem;
};

#define LOAD_SLICE(gs_) do {                                                     \
    const int c_ = (gs_) >> 3, sl_ = (gs_) & 7, q_ = (gs_) % 3;                  \
    const uint32_t kb_ = X.sb + SM_K + (uint32_t)q_ * 16384 + X.ldrow;           \
    const size_t sr_ = (size_t)(c_ * 128 + X.lr) * CK + sl_ * 32;                \
    CP_ASYNC16(kb_ + (X.ljb + 0) * 128,        X.khiP + sr_ + (X.ljb + 0) * 8);  \
    CP_ASYNC16(kb_ + (X.ljb + 1) * 128,        X.khiP + sr_ + (X.ljb + 1) * 8);  \
    CP_ASYNC16(kb_ + 8192 + (X.ljb + 0) * 128, X.kloP + sr_ + (X.ljb + 0) * 8);  \
    CP_ASYNC16(kb_ + 8192 + (X.ljb + 1) * 128, X.kloP + sr_ + (X.ljb + 1) * 8);  \
} while (0)

// One chunk: 8 slices of MMAs into accC; per slice, one nt-piece of the
// PREVIOUS chunk's epilogue (accP) if do_epi.
__device__ __forceinline__ void run_chunk(
    const Ctx& X, int c, bool do_epi, int vparity,
    float (&accC)[2][8][4], float (&accP)[2][8][4],
    float (&run_s)[2][2], float (&run_a)[2][2][3])
{
    #pragma unroll
    for (int sl = 0; sl < 8; ++sl) {
        const int gs = c * 8 + sl;
        CP_WAIT1();
        __syncthreads();

        if (sl == 0) {
            if (X.tid < 128) {
                // async V load; lands with the gs+2 commit group, read a full
                // chunk later -> latency hidden
                const float* vr = X.vP + (size_t)(c * 128 + X.tid) * CV;
                const uint32_t vdst = X.sb + SM_V + vparity * 2048 + X.tid * 16;
                CP_ASYNC4(vdst + 0, vr + 0);
                CP_ASYNC4(vdst + 4, vr + 1);
                CP_ASYNC4(vdst + 8, vr + 2);
            }
            #pragma unroll
            for (int mt = 0; mt < 2; ++mt)
                #pragma unroll
                for (int nt = 0; nt < 8; ++nt) {
                    accC[mt][nt][0] = 0.f; accC[mt][nt][1] = 0.f;
                    accC[mt][nt][2] = 0.f; accC[mt][nt][3] = 0.f;
                }
        }

        if (gs + 2 < 32) { LOAD_SLICE(gs + 2); }
        CP_COMMIT();

        const uint32_t kb = X.sb + SM_K + (uint32_t)(gs % 3) * 16384;
        #pragma unroll
        for (int kk = 0; kk < 2; ++kk) {
            uint32_t ah[2][4], al[2][4];
            const int t8k = sl * 4 + kk * 2 + X.grp_dk;
            #pragma unroll
            for (int mt = 0; mt < 2; ++mt) {
                const int tm8 = X.wm * 4 + mt * 2 + X.grp_d0;
                const uint32_t off = (uint32_t)((tm8 * 32 + t8k) * 128 + X.irow * 16);
                LDSM_X4(ah[mt][0], ah[mt][1], ah[mt][2], ah[mt][3], X.sb + SM_QHI + off);
                LDSM_X4(al[mt][0], al[mt][1], al[mt][2], al[mt][3], X.sb + SM_QLO + off);
            }
            uint32_t bh[8][2], bl[8][2];
            const int tk = kk * 2 + X.grp_dk;
            #pragma unroll
            for (int nf2 = 0; nf2 < 4; ++nf2) {
                const int tn = X.wn * 8 + nf2 * 2 + X.grp_d0;
                const uint32_t off = (uint32_t)((tn * 4 + tk) * 128 + X.irow * 16);
                uint32_t r0, r1, r2, r3;
                LDSM_X4(r0, r1, r2, r3, kb + off);
                bh[nf2 * 2][0] = r0;     bh[nf2 * 2][1] = r2;
                bh[nf2 * 2 + 1][0] = r1; bh[nf2 * 2 + 1][1] = r3;
                LDSM_X4(r0, r1, r2, r3, kb + 8192 + off);
                bl[nf2 * 2][0] = r0;     bl[nf2 * 2][1] = r2;
                bl[nf2 * 2 + 1][0] = r1; bl[nf2 * 2 + 1][1] = r3;
            }
            #pragma unroll
            for (int mt = 0; mt < 2; ++mt)
                #pragma unroll
                for (int nt = 0; nt < 8; ++nt) {
                    MMA_BF16(accC[mt][nt], ah[mt], bh[nt]);
                    MMA_BF16(accC[mt][nt], ah[mt], bl[nt]);
                    MMA_BF16(accC[mt][nt], al[mt], bh[nt]);
                }
        }

        // Distributed epilogue: nt = sl piece of the previous chunk.
        if (do_epi) {
            const float* vsm = (const float*)(X.smem + SM_V + (1 - vparity) * 2048);
            #pragma unroll
            for (int cc = 0; cc < 2; ++cc) {
                const int col = X.wn * 64 + sl * 8 + X.tau * 2 + cc;
                const float4 vv = *(const float4*)(vsm + col * 4);
                #pragma unroll
                for (int mt = 0; mt < 2; ++mt)
                    #pragma unroll
                    for (int h = 0; h < 2; ++h) {
                        const float e = ex2f(accP[mt][sl][h * 2 + cc] - SOFTMAX_SHIFT2);
                        run_s[mt][h] += e;
                        run_a[mt][h][0] = fmaf(e, vv.x, run_a[mt][h][0]);
                        run_a[mt][h][1] = fmaf(e, vv.y, run_a[mt][h][1]);
                        run_a[mt][h][2] = fmaf(e, vv.z, run_a[mt][h][2]);
                    }
            }
        }
    }
}

__global__ __launch_bounds__(256)
void fused_attn_kernel(const float* __restrict__ v, const float* __restrict__ m_v)
{
    extern __shared__ __align__(1024) char smem[];

    const int bm = blockIdx.x;          // query block 0..7
    const int p  = blockIdx.y;          // pair 0..55
    const int sp = blockIdx.z;          // split 0..2
    const int b = p / 7, t = p % 7;
    const int tid = threadIdx.x, wid = tid >> 5, lane = tid & 31;

    Ctx X;
    X.sb   = smem_u32(smem);
    X.smem = smem;
    X.tid  = tid;
    X.wm = wid & 3;
    X.wn = wid >> 2;
    X.grp_d0 = (lane >> 3) & 1;
    X.grp_dk = lane >> 4;
    X.irow   = lane & 7;
    X.tau    = lane & 3;
    const int g = lane >> 2;
    X.lr  = tid & 127;
    X.ljb = (tid >> 7) * 2;
    X.ldrow = (uint32_t)(((X.lr >> 3) * 4) * 128 + (X.lr & 7) * 16);

    // Source pointers
    const size_t qoff = ((size_t)(b * TT + t + 1) * HW + (size_t)bm * 128) * CK;
    const __nv_bfloat16* qhi = g_khi + qoff;
    const __nv_bfloat16* qlo = g_klo + qoff;
    if (sp < 2) {
        const size_t ko = ((size_t)(b * TT + t) * HW + (size_t)sp * 512) * CK;
        X.khiP = g_khi + ko; X.kloP = g_klo + ko;
        X.vP = v + ((size_t)(b * TT + t) * HW + (size_t)sp * 512) * CV;
    } else {
        const size_t ko = (size_t)(b * TT + t) * MEM * CK;
        X.khiP = g_mkhi + ko; X.kloP = g_mklo + ko;
        X.vP = m_v + (size_t)(b * TT + t) * MEM * CV;
    }

    // --- Prologue: load Q (hi + lo) ---
    {
        const int r = tid >> 1;
        const int jb0 = (tid & 1) * 16;
        const uint32_t drow = X.sb + (uint32_t)(((r >> 3) * 32) * 128 + (r & 7) * 16);
        const size_t srow = (size_t)r * CK;
        #pragma unroll
        for (int jj = 0; jj < 16; ++jj) {
            const int jb = jb0 + jj;
            CP_ASYNC16(drow + SM_QHI + jb * 128, qhi + srow + jb * 8);
        }
        #pragma unroll
        for (int jj = 0; jj < 16; ++jj) {
            const int jb = jb0 + jj;
            CP_ASYNC16(drow + SM_QLO + jb * 128, qlo + srow + jb * 8);
        }
    }
    CP_COMMIT();

    LOAD_SLICE(0); CP_COMMIT();
    LOAD_SLICE(1); CP_COMMIT();

    float accA[2][8][4], accB[2][8][4];
    float run_s[2][2], run_a[2][2][3];
    #pragma unroll
    for (int mt = 0; mt < 2; ++mt)
        #pragma unroll
        for (int h = 0; h < 2; ++h) {
            run_s[mt][h] = 0.f;
            run_a[mt][h][0] = 0.f; run_a[mt][h][1] = 0.f; run_a[mt][h][2] = 0.f;
        }

    // Four chunks, fully unrolled (straight-line; scheduler can pipeline
    // across chunk boundaries).
    run_chunk(X, 0, false, 0, accA, accB, run_s, run_a);
    run_chunk(X, 1, true,  1, accB, accA, run_s, run_a);
    run_chunk(X, 2, true,  0, accA, accB, run_s, run_a);
    run_chunk(X, 3, true,  1, accB, accA, run_s, run_a);

    // Final epilogue for the last chunk (accB, V parity 1)
    {
        const float* vsm = (const float*)(smem + SM_V + 1 * 2048);
        #pragma unroll
        for (int nt = 0; nt < 8; ++nt)
            #pragma unroll
            for (int cc = 0; cc < 2; ++cc) {
                const int col = X.wn * 64 + nt * 8 + X.tau * 2 + cc;
                const float4 vv = *(const float4*)(vsm + col * 4);
                #pragma unroll
                for (int mt = 0; mt < 2; ++mt)
                    #pragma unroll
                    for (int h = 0; h < 2; ++h) {
                        const float e = ex2f(accB[mt][nt][h * 2 + cc] - SOFTMAX_SHIFT2);
                        run_s[mt][h] += e;
                        run_a[mt][h][0] = fmaf(e, vv.x, run_a[mt][h][0]);
                        run_a[mt][h][1] = fmaf(e, vv.y, run_a[mt][h][1]);
                        run_a[mt][h][2] = fmaf(e, vv.z, run_a[mt][h][2]);
                    }
            }
    }

    // ---- final: quad-reduce lane partials, merge the two wn halves ----
    #pragma unroll
    for (int mt = 0; mt < 2; ++mt)
        #pragma unroll
        for (int h = 0; h < 2; ++h) {
            #pragma unroll
            for (int o = 1; o <= 2; o <<= 1) {
                run_s[mt][h]    += __shfl_xor_sync(0xffffffffu, run_s[mt][h], o);
                run_a[mt][h][0] += __shfl_xor_sync(0xffffffffu, run_a[mt][h][0], o);
                run_a[mt][h][1] += __shfl_xor_sync(0xffffffffu, run_a[mt][h][1], o);
                run_a[mt][h][2] += __shfl_xor_sync(0xffffffffu, run_a[mt][h][2], o);
            }
        }
    __syncthreads();
    float4* red = (float4*)(smem + SM_RED);     // [128]
    if (X.wn == 1 && X.tau == 0) {
        #pragma unroll
        for (int mt = 0; mt < 2; ++mt)
            #pragma unroll
            for (int h = 0; h < 2; ++h) {
                const int row = X.wm * 32 + mt * 16 + h * 8 + g;
                float4 w;
                w.x = run_s[mt][h];
                w.y = run_a[mt][h][0];
                w.z = run_a[mt][h][1];
                w.w = run_a[mt][h][2];
                red[row] = w;
            }
    }
    __syncthreads();
    if (X.wn == 0 && X.tau == 0) {
        #pragma unroll
        for (int mt = 0; mt < 2; ++mt)
            #pragma unroll
            for (int h = 0; h < 2; ++h) {
                const int row = X.wm * 32 + mt * 16 + h * 8 + g;
                const float4 w = red[row];
                float4 o;
                o.x = run_s[mt][h] + w.x;
                o.y = run_a[mt][h][0] + w.y;
                o.z = run_a[mt][h][1] + w.z;
                o.w = run_a[mt][h][2] + w.w;
                float4* dst = (float4*)(g_part +
                    ((size_t)sp * NQ + (size_t)p * HW + bm * 128 + row) * 4);
                *dst = o;
            }
    }
}

// ---------------------------------------------------------------------------
// Finish kernel: combine splits (first NQ threads) + ground-truth copy
// ---------------------------------------------------------------------------
__global__ __launch_bounds__(256)
void finish_kernel(const float* __restrict__ v, float* __restrict__ out)
{
    const int idx = blockIdx.x * 256 + threadIdx.x;
    const int total = NQ * CV;
    if (idx < total) {
        const int per_b = 7 * HW * CV;
        const int b = idx / per_b;
        const int r = idx - b * per_b;
        out[(size_t)total + idx] = v[(size_t)b * (TT * HW * CV) + (HW * CV) + r];
    }
    if (idx < NQ) {
        const float4 p0 = *(const float4*)(g_part + ((size_t)0 * NQ + idx) * 4);
        const float4 p1 = *(const float4*)(g_part + ((size_t)1 * NQ + idx) * 4);
        const float4 p2 = *(const float4*)(g_part + ((size_t)2 * NQ + idx) * 4);
        const float invk = (1.0f - COEF_MEM) / (p0.x + p1.x);
        const float invm = COEF_MEM / p2.x;
        float* o = out + (size_t)idx * CV;
        o[0] = (p0.y + p1.y) * invk + p2.y * invm;
        o[1] = (p0.z + p1.z) * invk + p2.z * invm;
        o[2] = (p0.w + p1.w) * invk + p2.w * invm;
    }
}

// ---------------------------------------------------------------------------
extern "C" void kernel_launch(void* const* d_in, const int* in_sizes, int n_in,
                              void* d_out, int out_size)
{
    const float* k   = (const float*)d_in[0];
    const float* v   = (const float*)d_in[1];
    const float* m_k = (const float*)d_in[2];
    const float* m_v = (const float*)d_in[3];
    float* out = (float*)d_out;

    (void)in_sizes; (void)n_in; (void)out_size;

    cudaFuncSetAttribute(fused_attn_kernel,
                         cudaFuncAttributeMaxDynamicSharedMemorySize, FUSED_SMEM);

    prep_kernel<<<(NK4 + NMK4 + 255) / 256, 256>>>(k, m_k);

    dim3 fgrid(HW / 128, NPAIR, 3);            // (8, 56, 3) = 1344 CTAs
    fused_attn_kernel<<<fgrid, 256, FUSED_SMEM>>>(v, m_v);

    finish_kernel<<<(NQ * CV + 255) / 256, 256>>>(v, out);
}

// round 15
// speedup vs baseline: 1.0797x; 1.0797x over previous
#include <cuda_runtime.h>
#include <cuda_bf16.h>
#include <math.h>
#include <stdint.h>

// Problem constants
#define BSZ   8
#define TT    8
#define HW    1024
#define CK    256
#define CV    3
#define MEM   512
#define NPAIR 56
#define NQ    (NPAIR * HW)     // 57344 queries total
#define COEF_MEM 0.2f
// k and m_k are pre-scaled by sqrt(log2(e)) in prep, so accumulated logits
// are logit*log2(e); softmax uses ex2 directly with a constant shift.
#define SQRT_LOG2E 1.20112240878645f
#define SOFTMAX_SHIFT2 57.7078016355585f   // 40 * log2(e)

// Scratch (static device arrays; no allocs)
__device__ __nv_bfloat16 g_khi[(size_t)BSZ * TT * HW * CK];
__device__ __nv_bfloat16 g_klo[(size_t)BSZ * TT * HW * CK];
__device__ __nv_bfloat16 g_mkhi[(size_t)BSZ * TT * MEM * CK];
__device__ __nv_bfloat16 g_mklo[(size_t)BSZ * TT * MEM * CK];
// Partial softmax state: [split 0..2][query][4] = {s, a0, a1, a2}
__device__ float g_part[(size_t)3 * NQ * 4];

// ---------------------------------------------------------------------------
// Baseline-PTX helpers (sm_80+ portable)
// ---------------------------------------------------------------------------
__device__ __forceinline__ uint32_t smem_u32(const void* p) {
    uint32_t a;
    asm("{ .reg .u64 t; cvta.to.shared.u64 t, %1; cvt.u32.u64 %0, t; }"
        : "=r"(a) : "l"(p));
    return a;
}

__device__ __forceinline__ float ex2f(float x) {
    float r;
    asm("ex2.approx.f32 %0, %1;" : "=f"(r) : "f"(x));
    return r;
}

#define CP_ASYNC16(dst, src) \
    asm volatile("cp.async.cg.shared.global [%0], [%1], 16;" \
                 :: "r"(dst), "l"(src))
#define CP_ASYNC4(dst, src) \
    asm volatile("cp.async.ca.shared.global [%0], [%1], 4;" \
                 :: "r"(dst), "l"(src))
#define CP_COMMIT() asm volatile("cp.async.commit_group;" ::: "memory")
#define CP_WAIT1()  asm volatile("cp.async.wait_group 1;" ::: "memory")

#define LDSM_X4(r0, r1, r2, r3, addr) \
    asm volatile("ldmatrix.sync.aligned.m8n8.x4.shared.b16 {%0,%1,%2,%3}, [%4];" \
                 : "=r"(r0), "=r"(r1), "=r"(r2), "=r"(r3) : "r"(addr))

#define MMA_BF16(d, a, b) \
    asm volatile("mma.sync.aligned.m16n8k16.row.col.f32.bf16.bf16.f32 " \
                 "{%0,%1,%2,%3}, {%4,%5,%6,%7}, {%8,%9}, {%0,%1,%2,%3};" \
                 : "+f"((d)[0]), "+f"((d)[1]), "+f"((d)[2]), "+f"((d)[3]) \
                 : "r"((a)[0]), "r"((a)[1]), "r"((a)[2]), "r"((a)[3]), \
                   "r"((b)[0]), "r"((b)[1]))

// ---------------------------------------------------------------------------
// Prep kernel (single launch): fp32 -> bf16 hi/lo split for k and m_k,
// pre-scaled by sqrt(log2(e)) so logits land in the exp2 domain.
// ---------------------------------------------------------------------------
#define NK4  ((BSZ * TT * HW * CK) / 4)
#define NMK4 ((BSZ * TT * MEM * CK) / 4)

__global__ __launch_bounds__(256)
void prep_kernel(const float* __restrict__ k, const float* __restrict__ m_k)
{
    int i = blockIdx.x * blockDim.x + threadIdx.x;
    const float* src;
    __nv_bfloat162 *hp, *lp;
    int idx;
    if (i < NK4) {
        src = k; idx = i;
        hp = (__nv_bfloat162*)g_khi; lp = (__nv_bfloat162*)g_klo;
    } else if (i < NK4 + NMK4) {
        src = m_k; idx = i - NK4;
        hp = (__nv_bfloat162*)g_mkhi; lp = (__nv_bfloat162*)g_mklo;
    } else {
        return;
    }
    float4 x = ((const float4*)src)[idx];
    x.x *= SQRT_LOG2E; x.y *= SQRT_LOG2E; x.z *= SQRT_LOG2E; x.w *= SQRT_LOG2E;
    __nv_bfloat16 h0 = __float2bfloat16(x.x), h1 = __float2bfloat16(x.y);
    __nv_bfloat16 h2 = __float2bfloat16(x.z), h3 = __float2bfloat16(x.w);
    __nv_bfloat16 l0 = __float2bfloat16(x.x - __bfloat162float(h0));
    __nv_bfloat16 l1 = __float2bfloat16(x.y - __bfloat162float(h1));
    __nv_bfloat16 l2 = __float2bfloat16(x.z - __bfloat162float(h2));
    __nv_bfloat16 l3 = __float2bfloat16(x.w - __bfloat162float(h3));
    hp[2 * idx] = {h0, h1}; hp[2 * idx + 1] = {h2, h3};
    lp[2 * idx] = {l0, l1}; lp[2 * idx + 1] = {l2, l3};
}

// ---------------------------------------------------------------------------
// Fused kernel: per CTA, 128 queries x 512 keys (one split).
// Per 128-key chunk: logits via 3-term bf16-split mma.sync; the (additive,
// constant-shift, exp2-domain) softmax epilogue of chunk c is DISTRIBUTED
// across the 8 slices of chunk c+1 (acc double-buffer).
// 8 warps = 4m x 2n, warp tile 32 rows x 64 cols.
// K streamed in 32-ck slices, triple-buffered cp.async. Q resident in SMEM.
// V loaded via cp.async (4B), consumed one chunk later (latency hidden).
// ---------------------------------------------------------------------------
#define SM_QHI 0
#define SM_QLO 65536
#define SM_K   131072               // 3 bufs x 16384 (hi 8KB + lo 8KB)
#define SM_V   180224               // 2 bufs x 128 x float4 = 4096
#define SM_RED 184320               // 2KB: [128] float4 for final merge
#define FUSED_SMEM 186368

struct Ctx {
    uint32_t sb;
    const __nv_bfloat16 *khiP, *kloP;
    const float* vP;
    int tid, wm, wn, grp_d0, grp_dk, irow, tau;
    int lr, ljb;
    uint32_t ldrow;
    char* smem;
};

#define LOAD_SLICE(gs_) do {                                                     \
    const int c_ = (gs_) >> 3, sl_ = (gs_) & 7, q_ = (gs_) % 3;                  \
    const uint32_t kb_ = X.sb + SM_K + (uint32_t)q_ * 16384 + X.ldrow;           \
    const size_t sr_ = (size_t)(c_ * 128 + X.lr) * CK + sl_ * 32;                \
    CP_ASYNC16(kb_ + (X.ljb + 0) * 128,        X.khiP + sr_ + (X.ljb + 0) * 8);  \
    CP_ASYNC16(kb_ + (X.ljb + 1) * 128,        X.khiP + sr_ + (X.ljb + 1) * 8);  \
    CP_ASYNC16(kb_ + 8192 + (X.ljb + 0) * 128, X.kloP + sr_ + (X.ljb + 0) * 8);  \
    CP_ASYNC16(kb_ + 8192 + (X.ljb + 1) * 128, X.kloP + sr_ + (X.ljb + 1) * 8);  \
} while (0)

// One chunk: 8 slices of MMAs into accC; per slice, one nt-piece of the
// PREVIOUS chunk's epilogue (accP) if do_epi.
__device__ __forceinline__ void run_chunk(
    const Ctx& X, int c, bool do_epi, int vparity,
    float (&accC)[2][8][4], float (&accP)[2][8][4],
    float (&run_s)[2][2], float (&run_a)[2][2][3])
{
    #pragma unroll
    for (int sl = 0; sl < 8; ++sl) {
        const int gs = c * 8 + sl;
        CP_WAIT1();
        __syncthreads();

        if (sl == 0) {
            if (X.tid < 128) {
                // async V load; lands with the gs+2 commit group, read a full
                // chunk later -> latency hidden
                const float* vr = X.vP + (size_t)(c * 128 + X.tid) * CV;
                const uint32_t vdst = X.sb + SM_V + vparity * 2048 + X.tid * 16;
                CP_ASYNC4(vdst + 0, vr + 0);
                CP_ASYNC4(vdst + 4, vr + 1);
                CP_ASYNC4(vdst + 8, vr + 2);
            }
            #pragma unroll
            for (int mt = 0; mt < 2; ++mt)
                #pragma unroll
                for (int nt = 0; nt < 8; ++nt) {
                    accC[mt][nt][0] = 0.f; accC[mt][nt][1] = 0.f;
                    accC[mt][nt][2] = 0.f; accC[mt][nt][3] = 0.f;
                }
        }

        if (gs + 2 < 32) { LOAD_SLICE(gs + 2); }
        CP_COMMIT();

        const uint32_t kb = X.sb + SM_K + (uint32_t)(gs % 3) * 16384;
        #pragma unroll
        for (int kk = 0; kk < 2; ++kk) {
            uint32_t ah[2][4], al[2][4];
            const int t8k = sl * 4 + kk * 2 + X.grp_dk;
            #pragma unroll
            for (int mt = 0; mt < 2; ++mt) {
                const int tm8 = X.wm * 4 + mt * 2 + X.grp_d0;
                const uint32_t off = (uint32_t)((tm8 * 32 + t8k) * 128 + X.irow * 16);
                LDSM_X4(ah[mt][0], ah[mt][1], ah[mt][2], ah[mt][3], X.sb + SM_QHI + off);
                LDSM_X4(al[mt][0], al[mt][1], al[mt][2], al[mt][3], X.sb + SM_QLO + off);
            }
            uint32_t bh[8][2], bl[8][2];
            const int tk = kk * 2 + X.grp_dk;
            #pragma unroll
            for (int nf2 = 0; nf2 < 4; ++nf2) {
                const int tn = X.wn * 8 + nf2 * 2 + X.grp_d0;
                const uint32_t off = (uint32_t)((tn * 4 + tk) * 128 + X.irow * 16);
                uint32_t r0, r1, r2, r3;
                LDSM_X4(r0, r1, r2, r3, kb + off);
                bh[nf2 * 2][0] = r0;     bh[nf2 * 2][1] = r2;
                bh[nf2 * 2 + 1][0] = r1; bh[nf2 * 2 + 1][1] = r3;
                LDSM_X4(r0, r1, r2, r3, kb + 8192 + off);
                bl[nf2 * 2][0] = r0;     bl[nf2 * 2][1] = r2;
                bl[nf2 * 2 + 1][0] = r1; bl[nf2 * 2 + 1][1] = r3;
            }
            #pragma unroll
            for (int mt = 0; mt < 2; ++mt)
                #pragma unroll
                for (int nt = 0; nt < 8; ++nt) {
                    MMA_BF16(accC[mt][nt], ah[mt], bh[nt]);
                    MMA_BF16(accC[mt][nt], ah[mt], bl[nt]);
                    MMA_BF16(accC[mt][nt], al[mt], bh[nt]);
                }
        }

        // Distributed epilogue: nt = sl piece of the previous chunk.
        if (do_epi) {
            const float* vsm = (const float*)(X.smem + SM_V + (1 - vparity) * 2048);
            #pragma unroll
            for (int cc = 0; cc < 2; ++cc) {
                const int col = X.wn * 64 + sl * 8 + X.tau * 2 + cc;
                const float4 vv = *(const float4*)(vsm + col * 4);
                #pragma unroll
                for (int mt = 0; mt < 2; ++mt)
                    #pragma unroll
                    for (int h = 0; h < 2; ++h) {
                        const float e = ex2f(accP[mt][sl][h * 2 + cc] - SOFTMAX_SHIFT2);
                        run_s[mt][h] += e;
                        run_a[mt][h][0] = fmaf(e, vv.x, run_a[mt][h][0]);
                        run_a[mt][h][1] = fmaf(e, vv.y, run_a[mt][h][1]);
                        run_a[mt][h][2] = fmaf(e, vv.z, run_a[mt][h][2]);
                    }
            }
        }
    }
}

__global__ __launch_bounds__(256)
void fused_attn_kernel(const float* __restrict__ v, const float* __restrict__ m_v)
{
    extern __shared__ __align__(1024) char smem[];

    const int bm = blockIdx.x;          // query block 0..7
    const int p  = blockIdx.y;          // pair 0..55
    const int sp = blockIdx.z;          // split 0..2
    const int b = p / 7, t = p % 7;
    const int tid = threadIdx.x, wid = tid >> 5, lane = tid & 31;

    Ctx X;
    X.sb   = smem_u32(smem);
    X.smem = smem;
    X.tid  = tid;
    X.wm = wid & 3;
    X.wn = wid >> 2;
    X.grp_d0 = (lane >> 3) & 1;
    X.grp_dk = lane >> 4;
    X.irow   = lane & 7;
    X.tau    = lane & 3;
    const int g = lane >> 2;
    X.lr  = tid & 127;
    X.ljb = (tid >> 7) * 2;
    X.ldrow = (uint32_t)(((X.lr >> 3) * 4) * 128 + (X.lr & 7) * 16);

    // Source pointers
    const size_t qoff = ((size_t)(b * TT + t + 1) * HW + (size_t)bm * 128) * CK;
    const __nv_bfloat16* qhi = g_khi + qoff;
    const __nv_bfloat16* qlo = g_klo + qoff;
    if (sp < 2) {
        const size_t ko = ((size_t)(b * TT + t) * HW + (size_t)sp * 512) * CK;
        X.khiP = g_khi + ko; X.kloP = g_klo + ko;
        X.vP = v + ((size_t)(b * TT + t) * HW + (size_t)sp * 512) * CV;
    } else {
        const size_t ko = (size_t)(b * TT + t) * MEM * CK;
        X.khiP = g_mkhi + ko; X.kloP = g_mklo + ko;
        X.vP = m_v + (size_t)(b * TT + t) * MEM * CV;
    }

    // --- Prologue: load Q (hi + lo) ---
    {
        const int r = tid >> 1;
        const int jb0 = (tid & 1) * 16;
        const uint32_t drow = X.sb + (uint32_t)(((r >> 3) * 32) * 128 + (r & 7) * 16);
        const size_t srow = (size_t)r * CK;
        #pragma unroll
        for (int jj = 0; jj < 16; ++jj) {
            const int jb = jb0 + jj;
            CP_ASYNC16(drow + SM_QHI + jb * 128, qhi + srow + jb * 8);
        }
        #pragma unroll
        for (int jj = 0; jj < 16; ++jj) {
            const int jb = jb0 + jj;
            CP_ASYNC16(drow + SM_QLO + jb * 128, qlo + srow + jb * 8);
        }
    }
    CP_COMMIT();

    LOAD_SLICE(0); CP_COMMIT();
    LOAD_SLICE(1); CP_COMMIT();

    float accA[2][8][4], accB[2][8][4];
    float run_s[2][2], run_a[2][2][3];
    #pragma unroll
    for (int mt = 0; mt < 2; ++mt)
        #pragma unroll
        for (int h = 0; h < 2; ++h) {
            run_s[mt][h] = 0.f;
            run_a[mt][h][0] = 0.f; run_a[mt][h][1] = 0.f; run_a[mt][h][2] = 0.f;
        }

    #pragma unroll 1
    for (int half = 0; half < 2; ++half) {
        run_chunk(X, half * 2 + 0, half > 0, 0, accA, accB, run_s, run_a);
        run_chunk(X, half * 2 + 1, true,     1, accB, accA, run_s, run_a);
    }

    // Final epilogue for the last chunk (accB, V parity 1)
    {
        const float* vsm = (const float*)(smem + SM_V + 1 * 2048);
        #pragma unroll
        for (int nt = 0; nt < 8; ++nt)
            #pragma unroll
            for (int cc = 0; cc < 2; ++cc) {
                const int col = X.wn * 64 + nt * 8 + X.tau * 2 + cc;
                const float4 vv = *(const float4*)(vsm + col * 4);
                #pragma unroll
                for (int mt = 0; mt < 2; ++mt)
                    #pragma unroll
                    for (int h = 0; h < 2; ++h) {
                        const float e = ex2f(accB[mt][nt][h * 2 + cc] - SOFTMAX_SHIFT2);
                        run_s[mt][h] += e;
                        run_a[mt][h][0] = fmaf(e, vv.x, run_a[mt][h][0]);
                        run_a[mt][h][1] = fmaf(e, vv.y, run_a[mt][h][1]);
                        run_a[mt][h][2] = fmaf(e, vv.z, run_a[mt][h][2]);
                    }
            }
    }

    // ---- final: quad-reduce lane partials, merge the two wn halves ----
    #pragma unroll
    for (int mt = 0; mt < 2; ++mt)
        #pragma unroll
        for (int h = 0; h < 2; ++h) {
            #pragma unroll
            for (int o = 1; o <= 2; o <<= 1) {
                run_s[mt][h]    += __shfl_xor_sync(0xffffffffu, run_s[mt][h], o);
                run_a[mt][h][0] += __shfl_xor_sync(0xffffffffu, run_a[mt][h][0], o);
                run_a[mt][h][1] += __shfl_xor_sync(0xffffffffu, run_a[mt][h][1], o);
                run_a[mt][h][2] += __shfl_xor_sync(0xffffffffu, run_a[mt][h][2], o);
            }
        }
    __syncthreads();
    float4* red = (float4*)(smem + SM_RED);     // [128]
    if (X.wn == 1 && X.tau == 0) {
        #pragma unroll
        for (int mt = 0; mt < 2; ++mt)
            #pragma unroll
            for (int h = 0; h < 2; ++h) {
                const int row = X.wm * 32 + mt * 16 + h * 8 + g;
                float4 w;
                w.x = run_s[mt][h];
                w.y = run_a[mt][h][0];
                w.z = run_a[mt][h][1];
                w.w = run_a[mt][h][2];
                red[row] = w;
            }
    }
    __syncthreads();
    if (X.wn == 0 && X.tau == 0) {
        #pragma unroll
        for (int mt = 0; mt < 2; ++mt)
            #pragma unroll
            for (int h = 0; h < 2; ++h) {
                const int row = X.wm * 32 + mt * 16 + h * 8 + g;
                const float4 w = red[row];
                float4 o;
                o.x = run_s[mt][h] + w.x;
                o.y = run_a[mt][h][0] + w.y;
                o.z = run_a[mt][h][1] + w.z;
                o.w = run_a[mt][h][2] + w.w;
                float4* dst = (float4*)(g_part +
                    ((size_t)sp * NQ + (size_t)p * HW + bm * 128 + row) * 4);
                *dst = o;
            }
    }
}

// ---------------------------------------------------------------------------
// Finish kernel: combine splits (first NQ threads) + ground-truth copy
// ---------------------------------------------------------------------------
__global__ __launch_bounds__(256)
void finish_kernel(const float* __restrict__ v, float* __restrict__ out)
{
    const int idx = blockIdx.x * 256 + threadIdx.x;
    const int total = NQ * CV;
    if (idx < total) {
        const int per_b = 7 * HW * CV;
        const int b = idx / per_b;
        const int r = idx - b * per_b;
        out[(size_t)total + idx] = v[(size_t)b * (TT * HW * CV) + (HW * CV) + r];
    }
    if (idx < NQ) {
        const float4 p0 = *(const float4*)(g_part + ((size_t)0 * NQ + idx) * 4);
        const float4 p1 = *(const float4*)(g_part + ((size_t)1 * NQ + idx) * 4);
        const float4 p2 = *(const float4*)(g_part + ((size_t)2 * NQ + idx) * 4);
        const float invk = (1.0f - COEF_MEM) / (p0.x + p1.x);
        const float invm = COEF_MEM / p2.x;
        float* o = out + (size_t)idx * CV;
        o[0] = (p0.y + p1.y) * invk + p2.y * invm;
        o[1] = (p0.z + p1.z) * invk + p2.z * invm;
        o[2] = (p0.w + p1.w) * invk + p2.w * invm;
    }
}

// ---------------------------------------------------------------------------
extern "C" void kernel_launch(void* const* d_in, const int* in_sizes, int n_in,
                              void* d_out, int out_size)
{
    const float* k   = (const float*)d_in[0];
    const float* v   = (const float*)d_in[1];
    const float* m_k = (const float*)d_in[2];
    const float* m_v = (const float*)d_in[3];
    float* out = (float*)d_out;

    (void)in_sizes; (void)n_in; (void)out_size;

    cudaFuncSetAttribute(fused_attn_kernel,
                         cudaFuncAttributeMaxDynamicSharedMemorySize, FUSED_SMEM);

    prep_kernel<<<(NK4 + NMK4 + 255) / 256, 256>>>(k, m_k);

    dim3 fgrid(HW / 128, NPAIR, 3);            // (8, 56, 3) = 1344 CTAs
    fused_attn_kernel<<<fgrid, 256, FUSED_SMEM>>>(v, m_v);

    finish_kernel<<<(NQ * CV + 255) / 256, 256>>>(v, out);
}

// round 16
// speedup vs baseline: 1.0916x; 1.0111x over previous
#include <cuda_runtime.h>
#include <cuda_bf16.h>
#include <math.h>
#include <stdint.h>

// Problem constants
#define BSZ   8
#define TT    8
#define HW    1024
#define CK    256
#define CV    3
#define MEM   512
#define NPAIR 56
#define NQ    (NPAIR * HW)     // 57344 queries total
#define COEF_MEM 0.2f
// k and m_k are pre-scaled by sqrt(log2(e)) in prep, so accumulated logits
// are logit*log2(e); softmax uses ex2 directly with a constant shift.
#define SQRT_LOG2E 1.20112240878645f
#define SOFTMAX_SHIFT2 57.7078016355585f   // 40 * log2(e)

// Scratch (static device arrays; no allocs)
__device__ __nv_bfloat16 g_khi[(size_t)BSZ * TT * HW * CK];
__device__ __nv_bfloat16 g_klo[(size_t)BSZ * TT * HW * CK];
__device__ __nv_bfloat16 g_mkhi[(size_t)BSZ * TT * MEM * CK];
__device__ __nv_bfloat16 g_mklo[(size_t)BSZ * TT * MEM * CK];
// Partial softmax state: [split 0..2][query][4] = {s, a0, a1, a2}
__device__ float g_part[(size_t)3 * NQ * 4];

// ---------------------------------------------------------------------------
// Baseline-PTX helpers (sm_80+ portable)
// ---------------------------------------------------------------------------
__device__ __forceinline__ uint32_t smem_u32(const void* p) {
    uint32_t a;
    asm("{ .reg .u64 t; cvta.to.shared.u64 t, %1; cvt.u32.u64 %0, t; }"
        : "=r"(a) : "l"(p));
    return a;
}

__device__ __forceinline__ float ex2f(float x) {
    float r;
    asm("ex2.approx.f32 %0, %1;" : "=f"(r) : "f"(x));
    return r;
}

#define CP_ASYNC16(dst, src) \
    asm volatile("cp.async.cg.shared.global [%0], [%1], 16;" \
                 :: "r"(dst), "l"(src))
#define CP_ASYNC4(dst, src) \
    asm volatile("cp.async.ca.shared.global [%0], [%1], 4;" \
                 :: "r"(dst), "l"(src))
#define CP_COMMIT() asm volatile("cp.async.commit_group;" ::: "memory")
#define CP_WAIT2()  asm volatile("cp.async.wait_group 2;" ::: "memory")

#define LDSM_X4(r0, r1, r2, r3, addr) \
    asm volatile("ldmatrix.sync.aligned.m8n8.x4.shared.b16 {%0,%1,%2,%3}, [%4];" \
                 : "=r"(r0), "=r"(r1), "=r"(r2), "=r"(r3) : "r"(addr))

#define MMA_BF16(d, a, b) \
    asm volatile("mma.sync.aligned.m16n8k16.row.col.f32.bf16.bf16.f32 " \
                 "{%0,%1,%2,%3}, {%4,%5,%6,%7}, {%8,%9}, {%0,%1,%2,%3};" \
                 : "+f"((d)[0]), "+f"((d)[1]), "+f"((d)[2]), "+f"((d)[3]) \
                 : "r"((a)[0]), "r"((a)[1]), "r"((a)[2]), "r"((a)[3]), \
                   "r"((b)[0]), "r"((b)[1]))

// ---------------------------------------------------------------------------
// Prep kernel (single launch): fp32 -> bf16 hi/lo split for k and m_k,
// pre-scaled by sqrt(log2(e)) so logits land in the exp2 domain.
// ---------------------------------------------------------------------------
#define NK4  ((BSZ * TT * HW * CK) / 4)
#define NMK4 ((BSZ * TT * MEM * CK) / 4)

__global__ __launch_bounds__(256)
void prep_kernel(const float* __restrict__ k, const float* __restrict__ m_k)
{
    int i = blockIdx.x * blockDim.x + threadIdx.x;
    const float* src;
    __nv_bfloat162 *hp, *lp;
    int idx;
    if (i < NK4) {
        src = k; idx = i;
        hp = (__nv_bfloat162*)g_khi; lp = (__nv_bfloat162*)g_klo;
    } else if (i < NK4 + NMK4) {
        src = m_k; idx = i - NK4;
        hp = (__nv_bfloat162*)g_mkhi; lp = (__nv_bfloat162*)g_mklo;
    } else {
        return;
    }
    float4 x = ((const float4*)src)[idx];
    x.x *= SQRT_LOG2E; x.y *= SQRT_LOG2E; x.z *= SQRT_LOG2E; x.w *= SQRT_LOG2E;
    __nv_bfloat16 h0 = __float2bfloat16(x.x), h1 = __float2bfloat16(x.y);
    __nv_bfloat16 h2 = __float2bfloat16(x.z), h3 = __float2bfloat16(x.w);
    __nv_bfloat16 l0 = __float2bfloat16(x.x - __bfloat162float(h0));
    __nv_bfloat16 l1 = __float2bfloat16(x.y - __bfloat162float(h1));
    __nv_bfloat16 l2 = __float2bfloat16(x.z - __bfloat162float(h2));
    __nv_bfloat16 l3 = __float2bfloat16(x.w - __bfloat162float(h3));
    hp[2 * idx] = {h0, h1}; hp[2 * idx + 1] = {h2, h3};
    lp[2 * idx] = {l0, l1}; lp[2 * idx + 1] = {l2, l3};
}

// ---------------------------------------------------------------------------
// Fused kernel: per CTA, 128 queries x 512 keys (one split).
// Per 128-key chunk: logits via 3-term bf16-split mma.sync; the (additive,
// constant-shift, exp2-domain) softmax epilogue of chunk c is DISTRIBUTED
// across the 8 slices of chunk c+1 (acc double-buffer).
// 8 warps = 4m x 2n, warp tile 32 rows x 64 cols.
// K streamed in 32-ck slices, QUAD-buffered cp.async, prefetch distance 3,
// wait_group 2 (two load groups in flight at every wait).
// Q resident in SMEM. V loaded via cp.async (4B), consumed one chunk later.
// ---------------------------------------------------------------------------
#define SM_QHI 0
#define SM_QLO 65536
#define SM_K   131072               // 4 bufs x 16384 (hi 8KB + lo 8KB)
#define SM_V   196608               // 2 bufs x 128 x float4 = 4096
#define SM_RED 200704               // 2KB: [128] float4 for final merge
#define FUSED_SMEM 202752           // 198 KB

struct Ctx {
    uint32_t sb;
    const __nv_bfloat16 *khiP, *kloP;
    const float* vP;
    int tid, wm, wn, grp_d0, grp_dk, irow, tau;
    int lr, ljb;
    uint32_t ldrow;
    char* smem;
};

#define LOAD_SLICE(gs_) do {                                                     \
    const int c_ = (gs_) >> 3, sl_ = (gs_) & 7, q_ = (gs_) & 3;                  \
    const uint32_t kb_ = X.sb + SM_K + (uint32_t)q_ * 16384 + X.ldrow;           \
    const size_t sr_ = (size_t)(c_ * 128 + X.lr) * CK + sl_ * 32;                \
    CP_ASYNC16(kb_ + (X.ljb + 0) * 128,        X.khiP + sr_ + (X.ljb + 0) * 8);  \
    CP_ASYNC16(kb_ + (X.ljb + 1) * 128,        X.khiP + sr_ + (X.ljb + 1) * 8);  \
    CP_ASYNC16(kb_ + 8192 + (X.ljb + 0) * 128, X.kloP + sr_ + (X.ljb + 0) * 8);  \
    CP_ASYNC16(kb_ + 8192 + (X.ljb + 1) * 128, X.kloP + sr_ + (X.ljb + 1) * 8);  \
} while (0)

// One chunk: 8 slices of MMAs into accC; per slice, one nt-piece of the
// PREVIOUS chunk's epilogue (accP) if do_epi.
__device__ __forceinline__ void run_chunk(
    const Ctx& X, int c, bool do_epi, int vparity,
    float (&accC)[2][8][4], float (&accP)[2][8][4],
    float (&run_s)[2][2], float (&run_a)[2][2][3])
{
    #pragma unroll
    for (int sl = 0; sl < 8; ++sl) {
        const int gs = c * 8 + sl;
        CP_WAIT2();
        __syncthreads();

        if (sl == 0) {
            if (X.tid < 128) {
                // async V load; lands with the gs+3 commit group, read a full
                // chunk later -> latency hidden
                const float* vr = X.vP + (size_t)(c * 128 + X.tid) * CV;
                const uint32_t vdst = X.sb + SM_V + vparity * 2048 + X.tid * 16;
                CP_ASYNC4(vdst + 0, vr + 0);
                CP_ASYNC4(vdst + 4, vr + 1);
                CP_ASYNC4(vdst + 8, vr + 2);
            }
            #pragma unroll
            for (int mt = 0; mt < 2; ++mt)
                #pragma unroll
                for (int nt = 0; nt < 8; ++nt) {
                    accC[mt][nt][0] = 0.f; accC[mt][nt][1] = 0.f;
                    accC[mt][nt][2] = 0.f; accC[mt][nt][3] = 0.f;
                }
        }

        if (gs + 3 < 32) { LOAD_SLICE(gs + 3); }
        CP_COMMIT();

        const uint32_t kb = X.sb + SM_K + (uint32_t)(gs & 3) * 16384;
        #pragma unroll
        for (int kk = 0; kk < 2; ++kk) {
            uint32_t ah[2][4], al[2][4];
            const int t8k = sl * 4 + kk * 2 + X.grp_dk;
            #pragma unroll
            for (int mt = 0; mt < 2; ++mt) {
                const int tm8 = X.wm * 4 + mt * 2 + X.grp_d0;
                const uint32_t off = (uint32_t)((tm8 * 32 + t8k) * 128 + X.irow * 16);
                LDSM_X4(ah[mt][0], ah[mt][1], ah[mt][2], ah[mt][3], X.sb + SM_QHI + off);
                LDSM_X4(al[mt][0], al[mt][1], al[mt][2], al[mt][3], X.sb + SM_QLO + off);
            }
            uint32_t bh[8][2], bl[8][2];
            const int tk = kk * 2 + X.grp_dk;
            #pragma unroll
            for (int nf2 = 0; nf2 < 4; ++nf2) {
                const int tn = X.wn * 8 + nf2 * 2 + X.grp_d0;
                const uint32_t off = (uint32_t)((tn * 4 + tk) * 128 + X.irow * 16);
                uint32_t r0, r1, r2, r3;
                LDSM_X4(r0, r1, r2, r3, kb + off);
                bh[nf2 * 2][0] = r0;     bh[nf2 * 2][1] = r2;
                bh[nf2 * 2 + 1][0] = r1; bh[nf2 * 2 + 1][1] = r3;
                LDSM_X4(r0, r1, r2, r3, kb + 8192 + off);
                bl[nf2 * 2][0] = r0;     bl[nf2 * 2][1] = r2;
                bl[nf2 * 2 + 1][0] = r1; bl[nf2 * 2 + 1][1] = r3;
            }
            #pragma unroll
            for (int mt = 0; mt < 2; ++mt)
                #pragma unroll
                for (int nt = 0; nt < 8; ++nt) {
                    MMA_BF16(accC[mt][nt], ah[mt], bh[nt]);
                    MMA_BF16(accC[mt][nt], ah[mt], bl[nt]);
                    MMA_BF16(accC[mt][nt], al[mt], bh[nt]);
                }
        }

        // Distributed epilogue: nt = sl piece of the previous chunk.
        if (do_epi) {
            const float* vsm = (const float*)(X.smem + SM_V + (1 - vparity) * 2048);
            #pragma unroll
            for (int cc = 0; cc < 2; ++cc) {
                const int col = X.wn * 64 + sl * 8 + X.tau * 2 + cc;
                const float4 vv = *(const float4*)(vsm + col * 4);
                #pragma unroll
                for (int mt = 0; mt < 2; ++mt)
                    #pragma unroll
                    for (int h = 0; h < 2; ++h) {
                        const float e = ex2f(accP[mt][sl][h * 2 + cc] - SOFTMAX_SHIFT2);
                        run_s[mt][h] += e;
                        run_a[mt][h][0] = fmaf(e, vv.x, run_a[mt][h][0]);
                        run_a[mt][h][1] = fmaf(e, vv.y, run_a[mt][h][1]);
                        run_a[mt][h][2] = fmaf(e, vv.z, run_a[mt][h][2]);
                    }
            }
        }
    }
}

__global__ __launch_bounds__(256)
void fused_attn_kernel(const float* __restrict__ v, const float* __restrict__ m_v)
{
    extern __shared__ __align__(1024) char smem[];

    const int bm = blockIdx.x;          // query block 0..7
    const int p  = blockIdx.y;          // pair 0..55
    const int sp = blockIdx.z;          // split 0..2
    const int b = p / 7, t = p % 7;
    const int tid = threadIdx.x, wid = tid >> 5, lane = tid & 31;

    Ctx X;
    X.sb   = smem_u32(smem);
    X.smem = smem;
    X.tid  = tid;
    X.wm = wid & 3;
    X.wn = wid >> 2;
    X.grp_d0 = (lane >> 3) & 1;
    X.grp_dk = lane >> 4;
    X.irow   = lane & 7;
    X.tau    = lane & 3;
    const int g = lane >> 2;
    X.lr  = tid & 127;
    X.ljb = (tid >> 7) * 2;
    X.ldrow = (uint32_t)(((X.lr >> 3) * 4) * 128 + (X.lr & 7) * 16);

    // Source pointers
    const size_t qoff = ((size_t)(b * TT + t + 1) * HW + (size_t)bm * 128) * CK;
    const __nv_bfloat16* qhi = g_khi + qoff;
    const __nv_bfloat16* qlo = g_klo + qoff;
    if (sp < 2) {
        const size_t ko = ((size_t)(b * TT + t) * HW + (size_t)sp * 512) * CK;
        X.khiP = g_khi + ko; X.kloP = g_klo + ko;
        X.vP = v + ((size_t)(b * TT + t) * HW + (size_t)sp * 512) * CV;
    } else {
        const size_t ko = (size_t)(b * TT + t) * MEM * CK;
        X.khiP = g_mkhi + ko; X.kloP = g_mklo + ko;
        X.vP = m_v + (size_t)(b * TT + t) * MEM * CV;
    }

    // --- Prologue: load Q (hi + lo) ---
    {
        const int r = tid >> 1;
        const int jb0 = (tid & 1) * 16;
        const uint32_t drow = X.sb + (uint32_t)(((r >> 3) * 32) * 128 + (r & 7) * 16);
        const size_t srow = (size_t)r * CK;
        #pragma unroll
        for (int jj = 0; jj < 16; ++jj) {
            const int jb = jb0 + jj;
            CP_ASYNC16(drow + SM_QHI + jb * 128, qhi + srow + jb * 8);
        }
        #pragma unroll
        for (int jj = 0; jj < 16; ++jj) {
            const int jb = jb0 + jj;
            CP_ASYNC16(drow + SM_QLO + jb * 128, qlo + srow + jb * 8);
        }
    }
    CP_COMMIT();

    LOAD_SLICE(0); CP_COMMIT();
    LOAD_SLICE(1); CP_COMMIT();
    LOAD_SLICE(2); CP_COMMIT();

    float accA[2][8][4], accB[2][8][4];
    float run_s[2][2], run_a[2][2][3];
    #pragma unroll
    for (int mt = 0; mt < 2; ++mt)
        #pragma unroll
        for (int h = 0; h < 2; ++h) {
            run_s[mt][h] = 0.f;
            run_a[mt][h][0] = 0.f; run_a[mt][h][1] = 0.f; run_a[mt][h][2] = 0.f;
        }

    #pragma unroll 1
    for (int half = 0; half < 2; ++half) {
        run_chunk(X, half * 2 + 0, half > 0, 0, accA, accB, run_s, run_a);
        run_chunk(X, half * 2 + 1, true,     1, accB, accA, run_s, run_a);
    }

    // Final epilogue for the last chunk (accB, V parity 1)
    {
        const float* vsm = (const float*)(smem + SM_V + 1 * 2048);
        #pragma unroll
        for (int nt = 0; nt < 8; ++nt)
            #pragma unroll
            for (int cc = 0; cc < 2; ++cc) {
                const int col = X.wn * 64 + nt * 8 + X.tau * 2 + cc;
                const float4 vv = *(const float4*)(vsm + col * 4);
                #pragma unroll
                for (int mt = 0; mt < 2; ++mt)
                    #pragma unroll
                    for (int h = 0; h < 2; ++h) {
                        const float e = ex2f(accB[mt][nt][h * 2 + cc] - SOFTMAX_SHIFT2);
                        run_s[mt][h] += e;
                        run_a[mt][h][0] = fmaf(e, vv.x, run_a[mt][h][0]);
                        run_a[mt][h][1] = fmaf(e, vv.y, run_a[mt][h][1]);
                        run_a[mt][h][2] = fmaf(e, vv.z, run_a[mt][h][2]);
                    }
            }
    }

    // ---- final: quad-reduce lane partials, merge the two wn halves ----
    #pragma unroll
    for (int mt = 0; mt < 2; ++mt)
        #pragma unroll
        for (int h = 0; h < 2; ++h) {
            #pragma unroll
            for (int o = 1; o <= 2; o <<= 1) {
                run_s[mt][h]    += __shfl_xor_sync(0xffffffffu, run_s[mt][h], o);
                run_a[mt][h][0] += __shfl_xor_sync(0xffffffffu, run_a[mt][h][0], o);
                run_a[mt][h][1] += __shfl_xor_sync(0xffffffffu, run_a[mt][h][1], o);
                run_a[mt][h][2] += __shfl_xor_sync(0xffffffffu, run_a[mt][h][2], o);
            }
        }
    __syncthreads();
    float4* red = (float4*)(smem + SM_RED);     // [128]
    if (X.wn == 1 && X.tau == 0) {
        #pragma unroll
        for (int mt = 0; mt < 2; ++mt)
            #pragma unroll
            for (int h = 0; h < 2; ++h) {
                const int row = X.wm * 32 + mt * 16 + h * 8 + g;
                float4 w;
                w.x = run_s[mt][h];
                w.y = run_a[mt][h][0];
                w.z = run_a[mt][h][1];
                w.w = run_a[mt][h][2];
                red[row] = w;
            }
    }
    __syncthreads();
    if (X.wn == 0 && X.tau == 0) {
        #pragma unroll
        for (int mt = 0; mt < 2; ++mt)
            #pragma unroll
            for (int h = 0; h < 2; ++h) {
                const int row = X.wm * 32 + mt * 16 + h * 8 + g;
                const float4 w = red[row];
                float4 o;
                o.x = run_s[mt][h] + w.x;
                o.y = run_a[mt][h][0] + w.y;
                o.z = run_a[mt][h][1] + w.z;
                o.w = run_a[mt][h][2] + w.w;
                float4* dst = (float4*)(g_part +
                    ((size_t)sp * NQ + (size_t)p * HW + bm * 128 + row) * 4);
                *dst = o;
            }
    }
}

// ---------------------------------------------------------------------------
// Finish kernel: combine splits (first NQ threads) + ground-truth copy
// ---------------------------------------------------------------------------
__global__ __launch_bounds__(256)
void finish_kernel(const float* __restrict__ v, float* __restrict__ out)
{
    const int idx = blockIdx.x * 256 + threadIdx.x;
    const int total = NQ * CV;
    if (idx < total) {
        const int per_b = 7 * HW * CV;
        const int b = idx / per_b;
        const int r = idx - b * per_b;
        out[(size_t)total + idx] = v[(size_t)b * (TT * HW * CV) + (HW * CV) + r];
    }
    if (idx < NQ) {
        const float4 p0 = *(const float4*)(g_part + ((size_t)0 * NQ + idx) * 4);
        const float4 p1 = *(const float4*)(g_part + ((size_t)1 * NQ + idx) * 4);
        const float4 p2 = *(const float4*)(g_part + ((size_t)2 * NQ + idx) * 4);
        const float invk = (1.0f - COEF_MEM) / (p0.x + p1.x);
        const float invm = COEF_MEM / p2.x;
        float* o = out + (size_t)idx * CV;
        o[0] = (p0.y + p1.y) * invk + p2.y * invm;
        o[1] = (p0.z + p1.z) * invk + p2.z * invm;
        o[2] = (p0.w + p1.w) * invk + p2.w * invm;
    }
}

// ---------------------------------------------------------------------------
extern "C" void kernel_launch(void* const* d_in, const int* in_sizes, int n_in,
                              void* d_out, int out_size)
{
    const float* k   = (const float*)d_in[0];
    const float* v   = (const float*)d_in[1];
    const float* m_k = (const float*)d_in[2];
    const float* m_v = (const float*)d_in[3];
    float* out = (float*)d_out;

    (void)in_sizes; (void)n_in; (void)out_size;

    cudaFuncSetAttribute(fused_attn_kernel,
                         cudaFuncAttributeMaxDynamicSharedMemorySize, FUSED_SMEM);

    prep_kernel<<<(NK4 + NMK4 + 255) / 256, 256>>>(k, m_k);

    dim3 fgrid(HW / 128, NPAIR, 3);            // (8, 56, 3) = 1344 CTAs
    fused_attn_kernel<<<fgrid, 256, FUSED_SMEM>>>(v, m_v);

    finish_kernel<<<(NQ * CV + 255) / 256, 256>>>(v, out);
}